// round 16
// baseline (speedup 1.0000x reference)
#include <cuda_runtime.h>
#include <cstdint>

// Problem dims (fixed)
#define BATCH 16384
#define DIM   1024

// ---- tcgen05 GEMM tiling: BK=16 (SW64), 6-deep pipeline ----
#define BM2 256
#define BN2 256
#define NT  64             // k-tiles per output tile (1024/16)
#define STAGES 6
#define TSZ 16384          // per-operand per-stage: 256 rows * 64B
#define A_OFF 1024
#define B_OFF (A_OFF + STAGES * TSZ)        // 99328
#define GEMM_SMEM (B_OFF + STAGES * TSZ)    // 197632 B (same as R15)
#define MBAR_OFF 16        // full[s] +s*16, empty[s] +s*16+8 (6 stages -> 96B)
#define TMEMF0_OFF 128     // D0 free (count 4: epi warps 0-3)
#define TMEMF1_OFF 144     // D1 free (count 4: epi warps 4-7)
#define TILED_OFF 160      // tile_done (count 1, flips once per tile)

// idesc: D=F32(1<<4), A=TF32(2<<7), B=TF32(2<<10), N=256 (32<<17), M=128 (8<<24)
#define IDESC_TF32 ((1u<<4) | (2u<<7) | (2u<<10) | (32u<<17) | (8u<<24))

// Scratch (device globals — allocation-free)
__device__ float g_xk[BATCH * DIM];
__device__ float g_xv[BATCH * DIM];
__device__ float g_xr[BATCH * DIM];
__device__ float g_K[BATCH * DIM];
__device__ float g_V[BATCH * DIM];
__device__ float g_rwkv[BATCH * DIM];    // blocked+swizzled
__device__ float g_R[BATCH * DIM];
__device__ float g_Wt[4 * DIM * DIM];    // tf32, transposed [N,K], blocked+swizzled

// ---------------------------------------------------------------------------
// arch-portable helpers
// ---------------------------------------------------------------------------
__device__ __forceinline__ float tf32_rna(float x) {
    unsigned u;
    asm("cvt.rna.tf32.f32 %0, %1;" : "=r"(u) : "f"(x));
    return __uint_as_float(u);
}
__device__ __forceinline__ uint32_t smem_u32(const void* p) {
    return (uint32_t)__cvta_generic_to_shared(p);
}
__device__ __forceinline__ void mbar_init(uint32_t a, uint32_t cnt) {
    asm volatile("mbarrier.init.shared.b64 [%0], %1;" :: "r"(a), "r"(cnt) : "memory");
}
__device__ __forceinline__ void mbar_wait(uint32_t a, uint32_t parity) {
    asm volatile(
        "{\n\t.reg .pred P;\n"
        "WL%=:\n\t"
        "mbarrier.try_wait.parity.acquire.cta.shared::cta.b64 P, [%0], %1, 0x989680;\n\t"
        "@P bra WD%=;\n\t"
        "bra WL%=;\n"
        "WD%=:\n\t}"
        :: "r"(a), "r"(parity) : "memory");
}
__device__ __forceinline__ void mbar_expect_tx(uint32_t a, uint32_t bytes) {
    asm volatile("mbarrier.arrive.expect_tx.shared.b64 _, [%0], %1;"
                 :: "r"(a), "r"(bytes) : "memory");
}
__device__ __forceinline__ void mbar_arrive(uint32_t a) {
    asm volatile("mbarrier.arrive.shared.b64 _, [%0];" :: "r"(a) : "memory");
}

// blocked+swizzled float offset for element (row, k): 16KB tiles of
// [256 rows][16 floats = 64B, SW64: chunk' = chunk ^ ((r>>1)&3)]
__device__ __forceinline__ size_t blk_off(int row, int k) {
    int mb = row >> 8, r = row & 255, kt = k >> 4, c = (k >> 2) & 3;
    return ((size_t)(mb * NT + kt) << 12) + (size_t)(r * 16)
         + (size_t)(((c ^ ((r >> 1) & 3)) << 2) + (k & 3));
}

// ---------------------------------------------------------------------------
// tcgen05 / cluster helpers — sm_103a ONLY
// ---------------------------------------------------------------------------
#if defined(__CUDA_ARCH_FEAT_SM103_ALL) || defined(__CUDA_ARCH_FEAT_SM100_ALL)
#define HAS_TCGEN05 1
#else
#define HAS_TCGEN05 0
#endif

#if HAS_TCGEN05
__device__ __forceinline__ uint32_t elect_one() {
    uint32_t p;
    asm volatile("{\n.reg .pred P;\nelect.sync _|P, 0xFFFFFFFF;\nselp.b32 %0, 1, 0, P;\n}" : "=r"(p));
    return p;
}
__device__ __forceinline__ uint32_t ctarank() {
    uint32_t r;
    asm("mov.u32 %0, %%cluster_ctarank;" : "=r"(r));
    return r;
}
__device__ __forceinline__ void bulk_self(uint32_t dst, const void* src, uint32_t bytes,
                                          uint32_t mbar) {
    asm volatile(
        "cp.async.bulk.shared::cta.global.mbarrier::complete_tx::bytes [%0], [%1], %2, [%3];"
        :: "r"(dst), "l"(src), "r"(bytes), "r"(mbar) : "memory");
}
__device__ __forceinline__ void bulk_mc(uint32_t dst, const void* src, uint32_t bytes,
                                        uint32_t mbar, uint32_t mask) {
    asm volatile(
        "cp.async.bulk.shared::cluster.global.mbarrier::complete_tx::bytes.multicast::cluster"
        " [%0], [%1], %2, [%3], %4;"
        :: "r"(dst), "l"(src), "r"(bytes), "r"(mbar), "h"((uint16_t)mask) : "memory");
}
// fire-and-forget L2 prefetch
__device__ __forceinline__ void bulk_prefetch_l2(const void* src, uint32_t bytes) {
    asm volatile("cp.async.bulk.prefetch.L2.global [%0], %1;" :: "l"(src), "r"(bytes));
}
// SW64 K-major descriptor: layout=4, version=1, SBO=32 (512B / 8 rows), LBO=1
__device__ __forceinline__ uint64_t make_desc(uint32_t addr) {
    const uint64_t base = (uint64_t(4) << 61) | (uint64_t(1) << 46)
                        | (uint64_t(32) << 32) | (uint64_t(1) << 16);
    return base | ((uint64_t)(addr >> 4) & 0x3FFF);
}
__device__ __forceinline__ void mma_tf32_ss(uint32_t d, uint64_t ad, uint64_t bd,
                                            uint32_t idesc, uint32_t en) {
    asm volatile(
        "{\n\t.reg .pred p;\n\t"
        "setp.ne.u32 p, %5, 0;\n\t"
        "tcgen05.mma.cta_group::1.kind::tf32 [%0], %1, %2, %3, {%4, %4, %4, %4}, p;\n\t}"
        :: "r"(d), "l"(ad), "l"(bd), "r"(idesc), "r"(0u), "r"(en) : "memory");
}
__device__ __forceinline__ void tc_commit_mc(uint32_t mbar, uint32_t mask) {
    asm volatile(
        "tcgen05.commit.cta_group::1.mbarrier::arrive::one.shared::cluster.multicast::cluster.b64 [%0], %1;"
        :: "r"(mbar), "h"((uint16_t)(mask)) : "memory");
}
__device__ __forceinline__ void tc_commit(uint32_t mbar) {
    asm volatile(
        "tcgen05.commit.cta_group::1.mbarrier::arrive::one.shared::cluster.b64 [%0];"
        :: "r"(mbar) : "memory");
}
#endif

// keeps ncu's fixed sample slot on gemm_tc_kernel
__global__ void dummy_kernel() {}

// ---------------------------------------------------------------------------
// Persistent warp-specialized tcgen05 tf32 GEMM, 2x2 cluster multicast,
// BK=16 / 6-stage pipeline (lookahead 5*512 cyc >= refill RTT).
// grid (4, 32, 1), 320 threads; p = (by>>1) + 16*i -> z=p>>5, mb=2*(p&31)+(by&1).
// Warps 0-7: epilogue. Warp 8: MMA issuer. Warp 9: producer (+L2 prefetch).
// ---------------------------------------------------------------------------
__global__ void __launch_bounds__(320, 1) __cluster_dims__(2, 2, 1)
gemm_tc_kernel(int num_z,
               const float* __restrict__ A0, const float* __restrict__ A1,
               const float* __restrict__ A2,
               const float* __restrict__ B0, const float* __restrict__ B1,
               const float* __restrict__ B2,
               float* __restrict__ C0, float* __restrict__ C1,
               float* __restrict__ C2)
{
#if HAS_TCGEN05
    extern __shared__ char smem[];
    const uint32_t sb = smem_u32(smem);

    const int tid = threadIdx.x;
    const int w = tid >> 5, lane = tid & 31;
    const int bx = blockIdx.x, by = blockIdx.y;
    const int pair = by >> 1;
    const int nb = bx;
    const int iters = 2 * num_z;

    const uint32_t rank = ctarank();
    const uint32_t a_half = rank & 1;
    const uint32_t b_half = (rank >> 1) & 1;
    const uint32_t maskA = (1u << rank) | (1u << (rank ^ 1));
    const uint32_t maskB = (1u << rank) | (1u << (rank ^ 2));
    const uint32_t cmask = (1u << rank) | (1u << (rank ^ 1)) | (1u << (rank ^ 2));

    const float* Aops[3] = {A0, A1, A2};
    const float* Bops[3] = {B0, B1, B2};
    float*       Cops[3] = {C0, C1, C2};

    // TMEM alloc (512 cols): warp 0 collective
    if (w == 0) {
        asm volatile("tcgen05.alloc.cta_group::1.sync.aligned.shared::cta.b32 [%0], %1;"
                     :: "r"(sb), "r"(512u) : "memory");
    }
    if (tid == 0) {
#pragma unroll
        for (int s = 0; s < STAGES; s++) {
            mbar_init(sb + MBAR_OFF + s * 16, 1);       // full
            mbar_init(sb + MBAR_OFF + s * 16 + 8, 3);   // empty: 3 multicast commits
        }
        mbar_init(sb + TMEMF0_OFF, 4);                   // D0 free: epi warps 0-3
        mbar_init(sb + TMEMF1_OFF, 4);                   // D1 free: epi warps 4-7
        mbar_init(sb + TILED_OFF, 1);                    // tile_done: 1 commit/tile
    }
    __syncthreads();
    uint32_t tmem;
    asm volatile("ld.shared.b32 %0, [%1];" : "=r"(tmem) : "r"(sb));

    // ---- early self-loads: k-tiles g=0,1 of tile 0 (pre-cluster-sync) ----
    if (w == 9) {
        if (elect_one()) {
            const int p0 = pair;                 // j = 0
            const int z0 = p0 >> 5;
            const int mb0 = 2 * (p0 & 31) + (by & 1);
            const char* Ab = (const char*)Aops[z0] + ((size_t)(mb0 * NT) << 14);
            const char* Bb = (const char*)Bops[z0] + ((size_t)(nb * NT) << 14);
#pragma unroll
            for (int t = 0; t < 2; t++) {
                mbar_expect_tx(sb + MBAR_OFF + t * 16, 32768u);
                bulk_self(sb + A_OFF + t * TSZ, Ab + ((size_t)t << 14), 16384u,
                          sb + MBAR_OFF + t * 16);
                bulk_self(sb + B_OFF + t * TSZ, Bb + ((size_t)t << 14), 16384u,
                          sb + MBAR_OFF + t * 16);
            }
        }
    }

    asm volatile("barrier.cluster.arrive.aligned;" ::: "memory");
    asm volatile("barrier.cluster.wait.aligned;" ::: "memory");

    if (w == 8) {
        // ---- MMA issuer ----
        if (elect_one()) {
            for (int j = 0; j < iters; j++) {
                for (int kt = 0; kt < NT; kt++) {
                    const int g = j * NT + kt;
                    const int st = g % STAGES;
                    mbar_wait(sb + MBAR_OFF + st * 16, (uint32_t)((g / STAGES) & 1));
                    uint64_t ad0 = make_desc(sb + A_OFF + st * TSZ);
                    uint64_t ad1 = make_desc(sb + A_OFF + st * TSZ + 8192);
                    uint64_t bd  = make_desc(sb + B_OFF + st * TSZ);
                    if (kt == 0) {
                        if (j > 0) mbar_wait(sb + TMEMF0_OFF, (uint32_t)((j - 1) & 1));
#pragma unroll
                        for (int ks = 0; ks < 2; ks++)
                            mma_tf32_ss(tmem, ad0 + ks * 2, bd + ks * 2, IDESC_TF32,
                                        ks == 0 ? 0u : 1u);
                        if (j > 0) mbar_wait(sb + TMEMF1_OFF, (uint32_t)((j - 1) & 1));
#pragma unroll
                        for (int ks = 0; ks < 2; ks++)
                            mma_tf32_ss(tmem + 256, ad1 + ks * 2, bd + ks * 2, IDESC_TF32,
                                        ks == 0 ? 0u : 1u);
                    } else {
#pragma unroll
                        for (int ks = 0; ks < 2; ks++) {
                            mma_tf32_ss(tmem,       ad0 + ks * 2, bd + ks * 2, IDESC_TF32, 1u);
                            mma_tf32_ss(tmem + 256, ad1 + ks * 2, bd + ks * 2, IDESC_TF32, 1u);
                        }
                    }
                    tc_commit_mc(sb + MBAR_OFF + st * 16 + 8, cmask);
                }
                tc_commit(sb + TILED_OFF);   // exactly once per tile
            }
        }
    } else if (w == 9) {
        // ---- producer: k-tiles g = 2 .. NT*iters-1 (multicast halves) ----
        if (elect_one()) {
            const int gend = NT * iters;
            for (int g = 2; g < gend; g++) {
                const int gp = g + 8;   // L2 prefetch, fire-and-forget
                if (gp < gend) {
                    const int jp = gp >> 6, ktp = gp & 63;
                    const int pp = pair + 16 * jp;
                    const int zp = pp >> 5;
                    const int mbp = 2 * (pp & 31) + (by & 1);
                    bulk_prefetch_l2((const char*)Aops[zp] + ((size_t)(mbp * NT) << 14)
                                     + ((size_t)ktp << 14) + (a_half << 13), 8192u);
                    bulk_prefetch_l2((const char*)Bops[zp] + ((size_t)(nb * NT) << 14)
                                     + ((size_t)ktp << 14) + (b_half << 13), 8192u);
                }
                const int st = g % STAGES;
                if (g >= STAGES)
                    mbar_wait(sb + MBAR_OFF + st * 16 + 8, (uint32_t)((g / STAGES - 1) & 1));
                const int j = g >> 6, kt = g & 63;
                const int p = pair + 16 * j;
                const int z = p >> 5;
                const int mb = 2 * (p & 31) + (by & 1);
                const char* Ab = (const char*)Aops[z] + ((size_t)(mb * NT) << 14);
                const char* Bb = (const char*)Bops[z] + ((size_t)(nb * NT) << 14);
                mbar_expect_tx(sb + MBAR_OFF + st * 16, 32768u);
                bulk_mc(sb + A_OFF + st * TSZ + a_half * 8192,
                        Ab + ((size_t)kt << 14) + (a_half << 13), 8192u,
                        sb + MBAR_OFF + st * 16, maskA);
                bulk_mc(sb + B_OFF + st * TSZ + b_half * 8192,
                        Bb + ((size_t)kt << 14) + (b_half << 13), 8192u,
                        sb + MBAR_OFF + st * 16, maskB);
            }
        }
    } else {
        // ---- epilogue warps 0-7 ----
        for (int j = 0; j < iters; j++) {
            mbar_wait(sb + TILED_OFF, (uint32_t)(j & 1));
            asm volatile("tcgen05.fence::after_thread_sync;" ::: "memory");

            const int p = pair + 16 * j;
            const int z = p >> 5;
            const int mb = 2 * (p & 31) + (by & 1);
            float* C = Cops[z];
            const int row0 = mb * BM2;
            const int col0 = nb * BN2;

            const uint32_t woff = (uint32_t)(w & 3) << 21;
            const uint32_t dbase = tmem + ((w >> 2) ? 256u : 0u) + woff;
            const int grow = row0 + (w >> 2) * 128 + (w & 3) * 32 + lane;
            float* crow = C + (long)grow * DIM + col0;
#pragma unroll
            for (int cb = 0; cb < 256; cb += 32) {
                uint32_t r[32];
                asm volatile(
                    "tcgen05.ld.sync.aligned.32x32b.x32.b32 "
                    "{%0,%1,%2,%3,%4,%5,%6,%7,%8,%9,%10,%11,%12,%13,%14,%15,"
                    "%16,%17,%18,%19,%20,%21,%22,%23,%24,%25,%26,%27,%28,%29,%30,%31}, [%32];"
                    : "=r"(r[0]), "=r"(r[1]), "=r"(r[2]), "=r"(r[3]),
                      "=r"(r[4]), "=r"(r[5]), "=r"(r[6]), "=r"(r[7]),
                      "=r"(r[8]), "=r"(r[9]), "=r"(r[10]), "=r"(r[11]),
                      "=r"(r[12]), "=r"(r[13]), "=r"(r[14]), "=r"(r[15]),
                      "=r"(r[16]), "=r"(r[17]), "=r"(r[18]), "=r"(r[19]),
                      "=r"(r[20]), "=r"(r[21]), "=r"(r[22]), "=r"(r[23]),
                      "=r"(r[24]), "=r"(r[25]), "=r"(r[26]), "=r"(r[27]),
                      "=r"(r[28]), "=r"(r[29]), "=r"(r[30]), "=r"(r[31])
                    : "r"(dbase + cb));
                asm volatile("tcgen05.wait::ld.sync.aligned;" ::: "memory");
#pragma unroll
                for (int q = 0; q < 32; q += 4)
                    *(float4*)(crow + cb + q) =
                        make_float4(__uint_as_float(r[q]), __uint_as_float(r[q + 1]),
                                    __uint_as_float(r[q + 2]), __uint_as_float(r[q + 3]));
            }
            if (elect_one())
                mbar_arrive(sb + ((w >> 2) ? TMEMF1_OFF : TMEMF0_OFF));
        }
    }

    __syncthreads();
    asm volatile("barrier.cluster.arrive.aligned;" ::: "memory");
    asm volatile("barrier.cluster.wait.aligned;" ::: "memory");
    if (w == 0) {
        asm volatile("tcgen05.relinquish_alloc_permit.cta_group::1.sync.aligned;");
        asm volatile("tcgen05.dealloc.cta_group::1.sync.aligned.b32 %0, %1;"
                     :: "r"(tmem), "r"(512u));
    }
#endif  // HAS_TCGEN05
}

// ---------------------------------------------------------------------------
// premix: xk/xv/xr = tf32(lerp) blocked; x passthrough
// ---------------------------------------------------------------------------
__global__ void __launch_bounds__(256)
premix_kernel(const float* __restrict__ x, const float* __restrict__ lx,
              const float* __restrict__ mk, const float* __restrict__ mv,
              const float* __restrict__ mr, float* __restrict__ x_out)
{
    const long i = ((long)blockIdx.x * 256 + threadIdx.x) * 4;
    const int row = (int)(i >> 10);
    const int k = (int)(i & (DIM - 1));
    const size_t off = blk_off(row, k);

    float4 xv4 = *(const float4*)(x + i);
    float4 lv4 = *(const float4*)(lx + i);
    *(float4*)(x_out + i) = xv4;

    float4 m, o;
    m = *(const float4*)(mk + k);
    o.x = tf32_rna(fmaf(xv4.x - lv4.x, m.x, lv4.x));
    o.y = tf32_rna(fmaf(xv4.y - lv4.y, m.y, lv4.y));
    o.z = tf32_rna(fmaf(xv4.z - lv4.z, m.z, lv4.z));
    o.w = tf32_rna(fmaf(xv4.w - lv4.w, m.w, lv4.w));
    *(float4*)(g_xk + off) = o;

    m = *(const float4*)(mv + k);
    o.x = tf32_rna(fmaf(xv4.x - lv4.x, m.x, lv4.x));
    o.y = tf32_rna(fmaf(xv4.y - lv4.y, m.y, lv4.y));
    o.z = tf32_rna(fmaf(xv4.z - lv4.z, m.z, lv4.z));
    o.w = tf32_rna(fmaf(xv4.w - lv4.w, m.w, lv4.w));
    *(float4*)(g_xv + off) = o;

    m = *(const float4*)(mr + k);
    o.x = tf32_rna(fmaf(xv4.x - lv4.x, m.x, lv4.x));
    o.y = tf32_rna(fmaf(xv4.y - lv4.y, m.y, lv4.y));
    o.z = tf32_rna(fmaf(xv4.z - lv4.z, m.z, lv4.z));
    o.w = tf32_rna(fmaf(xv4.w - lv4.w, m.w, lv4.w));
    *(float4*)(g_xr + off) = o;
}

// ---------------------------------------------------------------------------
// weight convert + transpose into blocked+swizzled [N,K] layout
// ---------------------------------------------------------------------------
__global__ void __launch_bounds__(256)
cvtw_kernel(const float* __restrict__ Wk, const float* __restrict__ Wv,
            const float* __restrict__ Wr, const float* __restrict__ Wout)
{
    __shared__ float t[32][33];
    const float* src;
    if (blockIdx.z == 0)      src = Wk;
    else if (blockIdx.z == 1) src = Wv;
    else if (blockIdx.z == 2) src = Wr;
    else                      src = Wout;
    float* dst = g_Wt + (size_t)blockIdx.z * DIM * DIM;

    const int kb = blockIdx.x * 32, nb = blockIdx.y * 32;
    const int tx = threadIdx.x & 31, ty = threadIdx.x >> 5;
#pragma unroll
    for (int r = ty; r < 32; r += 8)
        t[r][tx] = tf32_rna(src[(long)(kb + r) * DIM + nb + tx]);
    __syncthreads();
#pragma unroll
    for (int r = ty; r < 32; r += 8)
        dst[blk_off(nb + r, kb + tx)] = t[tx][r];
}

// ---------------------------------------------------------------------------
// elementwise RWKV recurrence
// ---------------------------------------------------------------------------
__global__ void __launch_bounds__(256)
rwkv_ew_kernel(const float* __restrict__ last_num, const float* __restrict__ last_den,
               const float* __restrict__ decay, const float* __restrict__ bonus,
               float* __restrict__ num_out, float* __restrict__ den_out)
{
    const long i = ((long)blockIdx.x * 256 + threadIdx.x) * 4;
    const int row = (int)(i >> 10);
    const int a = (int)(i & (DIM - 1));

    float4 kk = *(const float4*)(g_K + i);
    float4 vv = *(const float4*)(g_V + i);
    float4 rp = *(const float4*)(g_R + i);
    float4 ln = *(const float4*)(last_num + i);
    float4 ld = *(const float4*)(last_den + i);
    float4 bo = *(const float4*)(bonus + a);
    float4 de = *(const float4*)(decay + a);

    float4 rw, no, dn;
    {
        const float* kp = &kk.x; const float* vp = &vv.x; const float* rpp = &rp.x;
        const float* lnp = &ln.x; const float* ldp = &ld.x;
        const float* bop = &bo.x; const float* dep = &de.x;
        float* rwp = &rw.x; float* nop = &no.x; float* dnp = &dn.x;
#pragma unroll
        for (int t = 0; t < 4; t++) {
            float k = kp[t], v = vp[t];
            float ebk = expf(bop[t] + k);
            float wkv = (lnp[t] + ebk * v) / (ldp[t] + ebk);
            float r = 1.0f / (1.0f + expf(-rpp[t]));
            rwp[t] = tf32_rna(r * wkv);
            float w = expf(-expf(dep[t]));
            float ek = expf(k);
            nop[t] = w * lnp[t] + ek * v;
            dnp[t] = w * ldp[t] + ek;
        }
    }
    *(float4*)(g_rwkv + blk_off(row, a)) = rw;
    *(float4*)(num_out + i) = no;
    *(float4*)(den_out + i) = dn;
}

// ---------------------------------------------------------------------------
// Launch
// ---------------------------------------------------------------------------
extern "C" void kernel_launch(void* const* d_in, const int* in_sizes, int n_in,
                              void* d_out, int out_size)
{
    const float* x        = (const float*)d_in[0];
    const float* last_x   = (const float*)d_in[1];
    const float* last_num = (const float*)d_in[2];
    const float* last_den = (const float*)d_in[3];
    const float* mix_k    = (const float*)d_in[4];
    const float* mix_v    = (const float*)d_in[5];
    const float* mix_r    = (const float*)d_in[6];
    const float* decay    = (const float*)d_in[7];
    const float* bonus    = (const float*)d_in[8];
    const float* Wk       = (const float*)d_in[9];
    const float* Wv       = (const float*)d_in[10];
    const float* Wr       = (const float*)d_in[11];
    const float* Wout     = (const float*)d_in[12];

    float* out = (float*)d_out;
    const long BD = (long)BATCH * DIM;
    float* hidden_out = out;
    float* x_out      = out + BD;
    float* num_out    = out + 2 * BD;
    float* den_out    = out + 3 * BD;

    static bool attr_set = false;
    if (!attr_set) {
        cudaFuncSetAttribute(gemm_tc_kernel,
                             cudaFuncAttributeMaxDynamicSharedMemorySize, GEMM_SMEM);
        attr_set = true;
    }

    float *p_xk, *p_xv, *p_xr, *p_K, *p_V, *p_R, *p_rwkv, *p_Wt;
    cudaGetSymbolAddress((void**)&p_xk, g_xk);
    cudaGetSymbolAddress((void**)&p_xv, g_xv);
    cudaGetSymbolAddress((void**)&p_xr, g_xr);
    cudaGetSymbolAddress((void**)&p_K, g_K);
    cudaGetSymbolAddress((void**)&p_V, g_V);
    cudaGetSymbolAddress((void**)&p_R, g_R);
    cudaGetSymbolAddress((void**)&p_rwkv, g_rwkv);
    cudaGetSymbolAddress((void**)&p_Wt, g_Wt);

    // 1) premix (also writes x passthrough)
    premix_kernel<<<(unsigned)(BD / 4 / 256), 256>>>(x, last_x, mix_k, mix_v, mix_r, x_out);

    // 2) weight convert+transpose into blocked layout (tiny)
    dim3 gw(DIM / 32, DIM / 32, 4);
    cvtw_kernel<<<gw, 256>>>(Wk, Wv, Wr, Wout);

    // 2.5) dummy launch: keeps ncu's fixed sample position on gemm1
    dummy_kernel<<<1, 32>>>();

    // 3) K/V/R projections: persistent, z-folded (num_z=3 -> 6 tiles/CTA)
    dim3 grid1(4, 32, 1);
    gemm_tc_kernel<<<grid1, 320, GEMM_SMEM>>>(
        3,
        p_xk, p_xv, p_xr,
        p_Wt + 0L * DIM * DIM, p_Wt + 1L * DIM * DIM, p_Wt + 2L * DIM * DIM,
        p_K, p_V, p_R);

    // 4) elementwise recurrence
    rwkv_ew_kernel<<<(unsigned)(BD / 4 / 256), 256>>>(last_num, last_den, decay, bonus,
                                                      num_out, den_out);

    // 5) hidden = rwkv @ Wout (num_z=1 -> 2 tiles/CTA)
    dim3 grid2(4, 32, 1);
    gemm_tc_kernel<<<grid2, 320, GEMM_SMEM>>>(
        1,
        p_rwkv, p_rwkv, p_rwkv,
        p_Wt + 3L * DIM * DIM, p_Wt + 3L * DIM * DIM, p_Wt + 3L * DIM * DIM,
        hidden_out, hidden_out, hidden_out);
}